// round 13
// baseline (speedup 1.0000x reference)
#include <cuda_runtime.h>
#include <cstdint>

#define NROWS 65536
#define DOUT  128
#define DZ    64

#define GRID  304
#define TPB   256
#define NSTG  3

#define STAGE_FLOATS 8192             // 32 KB per stage
#define STAGE_BYTES  32768
#define DYN_BYTES    (NSTG * STAGE_BYTES)   // 98304

// roles (by bid parity: even=TMA, odd=LDG; sub = bid>>1 in [0,152))
//   TMA sub<76:  recon first half (output/target floats [0, 4194304))
//   TMA sub>=76: z-pair (full z, zt)
//   LDG sub<76:  KL (full logv, mean)
//   LDG sub>=76: recon second half (float4 idx [1048576, 2097152))
#define NB 76
#define CUT_T 36      // 1024 tiles = 13*76 + 36  (both TMA roles)

#define LDG_T   (NB * TPB)           // 19456 threads per LDG role
#define LM_TAIL 17408                // 1048576 f4 = 53*19456 + 17408
#define REC_HALF_F4 1048576          // start of LDG recon half (float4 units)

// Zero-initialized device globals (reset by last block each call -> replay-safe)
__device__ float        g_scal[2];      // [0]=KL elem sum, [1]=recon sq sum
__device__ float        g_col[5][DZ];   // Sz, Szt, Sz2, Szt2, Szp
__device__ unsigned int g_count;

__device__ __forceinline__ uint32_t smem_u32(const void* p) {
    return (uint32_t)__cvta_generic_to_shared((void*)p);
}
__device__ __forceinline__ void mbar_init(uint32_t a, uint32_t cnt) {
    asm volatile("mbarrier.init.shared.b64 [%0], %1;" :: "r"(a), "r"(cnt) : "memory");
}
__device__ __forceinline__ void mbar_expect(uint32_t a, uint32_t bytes) {
    asm volatile("mbarrier.arrive.expect_tx.shared.b64 _, [%0], %1;"
                 :: "r"(a), "r"(bytes) : "memory");
}
__device__ __forceinline__ void bulk_g2s(uint32_t dst, const float* src,
                                         uint32_t bytes, uint32_t mbar) {
    asm volatile(
        "cp.async.bulk.shared::cluster.global.mbarrier::complete_tx::bytes "
        "[%0], [%1], %2, [%3];"
        :: "r"(dst), "l"(src), "r"(bytes), "r"(mbar) : "memory");
}
__device__ __forceinline__ void mbar_wait(uint32_t a, uint32_t parity) {
    asm volatile(
        "{\n\t"
        ".reg .pred P1;\n\t"
        "LAB_WAIT_%=:\n\t"
        "mbarrier.try_wait.parity.acquire.cta.shared::cta.b64 P1, [%0], %1, 0x989680;\n\t"
        "@P1 bra LAB_DONE_%=;\n\t"
        "bra LAB_WAIT_%=;\n\t"
        "LAB_DONE_%=:\n\t"
        "}"
        :: "r"(a), "r"(parity) : "memory");
}

__device__ __forceinline__ void kl_acc(const float4& L, const float4& M, float& a) {
    a += (L.x - __expf(L.x) - M.x * M.x + 1.0f);
    a += (L.y - __expf(L.y) - M.y * M.y + 1.0f);
    a += (L.z - __expf(L.z) - M.z * M.z + 1.0f);
    a += (L.w - __expf(L.w) - M.w * M.w + 1.0f);
}
__device__ __forceinline__ void rec_acc(const float4& O, const float4& T, float& b) {
    float d0 = O.x - T.x, d1 = O.y - T.y, d2 = O.z - T.z, d3 = O.w - T.w;
    b += d0 * d0 + d1 * d1 + d2 * d2 + d3 * d3;
}

extern __shared__ float dyn[];   // NSTG stages of 8192 floats

__global__ void __launch_bounds__(TPB) vde_fused_kernel(
    const float* __restrict__ target,
    const float* __restrict__ output,
    const float* __restrict__ mean,
    const float* __restrict__ logv,
    const float* __restrict__ z,
    const float* __restrict__ zt,
    float* __restrict__ out)
{
    __shared__ __align__(8) unsigned long long mbar_s[NSTG];
    __shared__ float s_part[8][320];
    __shared__ float s_ab[8];

    const int bid  = blockIdx.x;
    const int t    = threadIdx.x;
    const int lane = t & 31;
    const int warp = t >> 5;

    const bool tma_path = !(bid & 1);
    const int  sub = bid >> 1;           // 0..151

    if (tma_path) {
        uint32_t mb[NSTG];
        #pragma unroll
        for (int s = 0; s < NSTG; s++) mb[s] = smem_u32(&mbar_s[s]);
        if (t == 0) {
            #pragma unroll
            for (int s = 0; s < NSTG; s++) mbar_init(mb[s], 1);
        }
        __syncthreads();
        unsigned pbits = 0;

        const bool is_rec = (sub < NB);
        const int  ridx   = is_rec ? sub : (sub - NB);
        const int  nt     = 13 + (ridx < CUT_T);
        const float* A = is_rec ? output : z;
        const float* B = is_rec ? target : zt;

        if (t == 0) {
            for (int k = 0; k < NSTG; k++) {
                size_t off = (size_t)(ridx + k * NB) * 4096;
                uint32_t d = smem_u32(&dyn[k * STAGE_FLOATS]);
                mbar_expect(mb[k], STAGE_BYTES);
                bulk_g2s(d,         A + off, 16384, mb[k]);
                bulk_g2s(d + 16384, B + off, 16384, mb[k]);
            }
        }

        if (is_rec) {
            float b = 0.0f;
            int s = 0;
            for (int k = 0; k < nt; k++) {
                mbar_wait(mb[s], (pbits >> s) & 1u);
                pbits ^= (1u << s);
                const float4* base = (const float4*)&dyn[s * STAGE_FLOATS];
                #pragma unroll
                for (int j = 0; j < 4; j++)
                    rec_acc(base[j * 256 + t], base[1024 + j * 256 + t], b);
                __syncthreads();
                if (t == 0 && k + NSTG < nt) {
                    size_t off = (size_t)(ridx + (k + NSTG) * NB) * 4096;
                    uint32_t d = smem_u32(&dyn[s * STAGE_FLOATS]);
                    mbar_expect(mb[s], STAGE_BYTES);
                    bulk_g2s(d,         A + off, 16384, mb[s]);
                    bulk_g2s(d + 16384, B + off, 16384, mb[s]);
                }
                s = (s == NSTG - 1) ? 0 : s + 1;
            }
            #pragma unroll
            for (int off = 16; off; off >>= 1)
                b += __shfl_down_sync(0xFFFFFFFFu, b, off);
            if (lane == 0) s_ab[warp] = b;
            __syncthreads();
            if (t == 0) {
                float tb = 0.0f;
                #pragma unroll
                for (int w = 0; w < 8; w++) tb += s_ab[w];
                atomicAdd(&g_scal[1], tb);
            }
        } else {
            float st[5][4] = {{0}};
            int s = 0;
            for (int k = 0; k < nt; k++) {
                mbar_wait(mb[s], (pbits >> s) & 1u);
                pbits ^= (1u << s);
                const float4* base = (const float4*)&dyn[s * STAGE_FLOATS];
                #pragma unroll
                for (int j = 0; j < 4; j++) {
                    float4 U = base[         j * 256 + t];
                    float4 V = base[1024 +   j * 256 + t];
                    st[0][0] += U.x; st[1][0] += V.x; st[2][0] += U.x * U.x; st[3][0] += V.x * V.x; st[4][0] += U.x * V.x;
                    st[0][1] += U.y; st[1][1] += V.y; st[2][1] += U.y * U.y; st[3][1] += V.y * V.y; st[4][1] += U.y * V.y;
                    st[0][2] += U.z; st[1][2] += V.z; st[2][2] += U.z * U.z; st[3][2] += V.z * V.z; st[4][2] += U.z * V.z;
                    st[0][3] += U.w; st[1][3] += V.w; st[2][3] += U.w * U.w; st[3][3] += V.w * V.w; st[4][3] += U.w * V.w;
                }
                __syncthreads();
                if (t == 0 && k + NSTG < nt) {
                    size_t off = (size_t)(ridx + (k + NSTG) * NB) * 4096;
                    uint32_t d = smem_u32(&dyn[s * STAGE_FLOATS]);
                    mbar_expect(mb[s], STAGE_BYTES);
                    bulk_g2s(d,         A + off, 16384, mb[s]);
                    bulk_g2s(d + 16384, B + off, 16384, mb[s]);
                }
                s = (s == NSTG - 1) ? 0 : s + 1;
            }
            #pragma unroll
            for (int si = 0; si < 5; si++)
                #pragma unroll
                for (int c = 0; c < 4; c++)
                    st[si][c] += __shfl_xor_sync(0xFFFFFFFFu, st[si][c], 16);
            if (lane < 16) {
                #pragma unroll
                for (int si = 0; si < 5; si++)
                    #pragma unroll
                    for (int c = 0; c < 4; c++)
                        s_part[warp][(si * 4 + c) * 16 + lane] = st[si][c];
            }
            __syncthreads();
            for (int idx = t; idx < 320; idx += TPB) {
                float v = 0.0f;
                #pragma unroll
                for (int w = 0; w < 8; w++) v += s_part[w][idx];
                int si  = idx >> 6;
                int rem = idx & 63;
                int c   = rem >> 4;
                int l   = rem & 15;
                atomicAdd(&g_col[si][l * 4 + c], v);
            }
        }
    } else {
        // =================== LDG path =========================================
        __syncthreads();   // match TMA-path barrier count (none needed, but harmless symmetry)
        const bool is_kl = (sub < NB);
        const int  ridx  = is_kl ? sub : (sub - NB);
        const int  g     = ridx * TPB + t;       // 0..19455
        float acc = 0.0f;

        if (is_kl) {
            const float4* lv4 = (const float4*)logv;
            const float4* m4  = (const float4*)mean;
            int i = g;
            #pragma unroll
            for (int kk = 0; kk < 13; kk++) {
                float4 L0 = __ldcs(lv4 + i);
                float4 M0 = __ldcs(m4  + i);
                float4 L1 = __ldcs(lv4 + i +     LDG_T);
                float4 M1 = __ldcs(m4  + i +     LDG_T);
                float4 L2 = __ldcs(lv4 + i + 2 * LDG_T);
                float4 M2 = __ldcs(m4  + i + 2 * LDG_T);
                float4 L3 = __ldcs(lv4 + i + 3 * LDG_T);
                float4 M3 = __ldcs(m4  + i + 3 * LDG_T);
                kl_acc(L0, M0, acc); kl_acc(L1, M1, acc);
                kl_acc(L2, M2, acc); kl_acc(L3, M3, acc);
                i += 4 * LDG_T;
            }
            { float4 L = __ldcs(lv4 + i), M = __ldcs(m4 + i); kl_acc(L, M, acc); i += LDG_T; }
            if (g < LM_TAIL) { float4 L = __ldcs(lv4 + i), M = __ldcs(m4 + i); kl_acc(L, M, acc); }
        } else {
            const float4* o4 = (const float4*)output + REC_HALF_F4;
            const float4* t4 = (const float4*)target + REC_HALF_F4;
            int i = g;
            #pragma unroll
            for (int kk = 0; kk < 13; kk++) {
                float4 O0 = __ldcs(o4 + i);
                float4 T0 = __ldcs(t4 + i);
                float4 O1 = __ldcs(o4 + i +     LDG_T);
                float4 T1 = __ldcs(t4 + i +     LDG_T);
                float4 O2 = __ldcs(o4 + i + 2 * LDG_T);
                float4 T2 = __ldcs(t4 + i + 2 * LDG_T);
                float4 O3 = __ldcs(o4 + i + 3 * LDG_T);
                float4 T3 = __ldcs(t4 + i + 3 * LDG_T);
                rec_acc(O0, T0, acc); rec_acc(O1, T1, acc);
                rec_acc(O2, T2, acc); rec_acc(O3, T3, acc);
                i += 4 * LDG_T;
            }
            { float4 O = __ldcs(o4 + i), T = __ldcs(t4 + i); rec_acc(O, T, acc); i += LDG_T; }
            if (g < LM_TAIL) { float4 O = __ldcs(o4 + i), T = __ldcs(t4 + i); rec_acc(O, T, acc); }
        }

        #pragma unroll
        for (int off = 16; off; off >>= 1)
            acc += __shfl_down_sync(0xFFFFFFFFu, acc, off);
        if (lane == 0) s_ab[warp] = acc;
        __syncthreads();
        if (t == 0) {
            float ta = 0.0f;
            #pragma unroll
            for (int w = 0; w < 8; w++) ta += s_ab[w];
            atomicAdd(&g_scal[is_kl ? 0 : 1], ta);
        }
    }

    // ================= last block finalizes + resets ==========================
    __shared__ unsigned int s_rank;
    __threadfence();
    __syncthreads();
    if (t == 0) s_rank = atomicAdd(&g_count, 1u);
    __syncthreads();
    if (s_rank != GRID - 1) return;

    __threadfence();

    __shared__ float sc[2], ss[2];
    if (t < DZ) {
        const int d = t;
        const float invN = 1.0f / (float)NROWS;
        float Sz   = *((volatile float*)&g_col[0][d]);
        float Szt  = *((volatile float*)&g_col[1][d]);
        float Sz2  = *((volatile float*)&g_col[2][d]);
        float Szt2 = *((volatile float*)&g_col[3][d]);
        float Szp  = *((volatile float*)&g_col[4][d]);

        float mu = Sz * invN, nu = Szt * invN;
        float cov  = Szp * invN - mu * nu;
        float vart = (Sz2  - (float)NROWS * mu * mu) / (float)(NROWS - 1);
        float varu = (Szt2 - (float)NROWS * nu * nu) / (float)(NROWS - 1);
        float sp = sqrtf(fmaxf(vart * varu, 0.0f));

        #pragma unroll
        for (int off = 16; off; off >>= 1) {
            cov += __shfl_down_sync(0xFFFFFFFFu, cov, off);
            sp  += __shfl_down_sync(0xFFFFFFFFu, sp,  off);
        }
        if (lane == 0) { sc[warp] = cov; ss[warp] = sp; }
    }
    __syncthreads();

    if (t == 0) {
        const float invN = 1.0f / (float)NROWS;
        float num = sc[0] + sc[1];
        float dot = ss[0] + ss[1];
        float kl    = -0.5f * (*((volatile float*)&g_scal[0])) * invN;
        float recon = (*((volatile float*)&g_scal[1])) / (float)((long long)NROWS * DOUT);
        out[0] = recon + kl - num / dot;
    }
    __syncthreads();

    for (int i = t; i < 5 * DZ; i += TPB) ((float*)g_col)[i] = 0.0f;
    if (t == 0) { g_scal[0] = 0.0f; g_scal[1] = 0.0f; g_count = 0u; }
}

extern "C" void kernel_launch(void* const* d_in, const int* in_sizes, int n_in,
                              void* d_out, int out_size) {
    (void)in_sizes; (void)n_in; (void)out_size;
    cudaFuncSetAttribute(vde_fused_kernel,
                         cudaFuncAttributeMaxDynamicSharedMemorySize, DYN_BYTES);
    vde_fused_kernel<<<GRID, TPB, DYN_BYTES>>>(
        (const float*)d_in[0], (const float*)d_in[1],
        (const float*)d_in[2], (const float*)d_in[3],
        (const float*)d_in[4], (const float*)d_in[5],
        (float*)d_out);
}

// round 14
// speedup vs baseline: 1.1530x; 1.1530x over previous
#include <cuda_runtime.h>
#include <cstdint>

#define NROWS 65536
#define DOUT  128
#define DZ    64

#define GRID  304
#define TPB   512
#define NSTG  3

#define STAGE_FLOATS 8192             // 32 KB per stage
#define STAGE_BYTES  32768
#define DYN_BYTES    (NSTG * STAGE_BYTES)   // 98304

// roles by bid: [0,137) recon-TMA, [137,228) z-TMA, [228,304) LDG
#define NB_RT 137
#define NB_ZT 91
#define NB_LDG 76

#define RT_TILES 1536   // recon tiles on TMA path (f4 [0, 1572864) per array)
#define ZT_TILES 1024   // z tiles (full 32 MB)
#define CUT_RT 29       // 1536 = 11*137 + 29
#define CUT_ZT 23       // 1024 = 11*91  + 23

#define LDG_T   (NB_LDG * TPB)       // 38912 threads
#define KL_TAIL 36864                // 1048576 = 26*38912 + 36864
#define RS_BASE 1572864              // LDG recon slice start (float4)
#define RS_TAIL 18432                // 524288 = 13*38912 + 18432

// Zero-initialized device globals (reset by last block each call -> replay-safe)
__device__ float        g_scal[2];      // [0]=KL elem sum, [1]=recon sq sum
__device__ float        g_col[5][DZ];   // Sz, Szt, Sz2, Szt2, Szp
__device__ unsigned int g_count;

__device__ __forceinline__ uint32_t smem_u32(const void* p) {
    return (uint32_t)__cvta_generic_to_shared((void*)p);
}
__device__ __forceinline__ void mbar_init(uint32_t a, uint32_t cnt) {
    asm volatile("mbarrier.init.shared.b64 [%0], %1;" :: "r"(a), "r"(cnt) : "memory");
}
__device__ __forceinline__ void mbar_expect(uint32_t a, uint32_t bytes) {
    asm volatile("mbarrier.arrive.expect_tx.shared.b64 _, [%0], %1;"
                 :: "r"(a), "r"(bytes) : "memory");
}
__device__ __forceinline__ void bulk_g2s(uint32_t dst, const float* src,
                                         uint32_t bytes, uint32_t mbar) {
    asm volatile(
        "cp.async.bulk.shared::cluster.global.mbarrier::complete_tx::bytes "
        "[%0], [%1], %2, [%3];"
        :: "r"(dst), "l"(src), "r"(bytes), "r"(mbar) : "memory");
}
__device__ __forceinline__ void mbar_wait(uint32_t a, uint32_t parity) {
    asm volatile(
        "{\n\t"
        ".reg .pred P1;\n\t"
        "LAB_WAIT_%=:\n\t"
        "mbarrier.try_wait.parity.acquire.cta.shared::cta.b64 P1, [%0], %1, 0x989680;\n\t"
        "@P1 bra LAB_DONE_%=;\n\t"
        "bra LAB_WAIT_%=;\n\t"
        "LAB_DONE_%=:\n\t"
        "}"
        :: "r"(a), "r"(parity) : "memory");
}

__device__ __forceinline__ void kl_acc(const float4& L, const float4& M, float& a) {
    a += (L.x - __expf(L.x) - M.x * M.x + 1.0f);
    a += (L.y - __expf(L.y) - M.y * M.y + 1.0f);
    a += (L.z - __expf(L.z) - M.z * M.z + 1.0f);
    a += (L.w - __expf(L.w) - M.w * M.w + 1.0f);
}
__device__ __forceinline__ void rec_acc(const float4& O, const float4& T, float& b) {
    float d0 = O.x - T.x, d1 = O.y - T.y, d2 = O.z - T.z, d3 = O.w - T.w;
    b += d0 * d0 + d1 * d1 + d2 * d2 + d3 * d3;
}

extern __shared__ float dyn[];   // NSTG stages of 8192 floats

__global__ void __launch_bounds__(TPB) vde_fused_kernel(
    const float* __restrict__ target,
    const float* __restrict__ output,
    const float* __restrict__ mean,
    const float* __restrict__ logv,
    const float* __restrict__ z,
    const float* __restrict__ zt,
    float* __restrict__ out)
{
    __shared__ __align__(8) unsigned long long mbar_s[NSTG];
    __shared__ float s_col[5][DZ];
    __shared__ float s_ab[16];

    const int bid  = blockIdx.x;
    const int t    = threadIdx.x;
    const int lane = t & 31;
    const int warp = t >> 5;

    if (bid < NB_RT + NB_ZT) {
        // =================== TMA path =========================================
        uint32_t mb[NSTG];
        #pragma unroll
        for (int s = 0; s < NSTG; s++) mb[s] = smem_u32(&mbar_s[s]);
        if (t == 0) {
            #pragma unroll
            for (int s = 0; s < NSTG; s++) mbar_init(mb[s], 1);
        }
        const bool is_rec = (bid < NB_RT);
        const int  ridx   = is_rec ? bid : (bid - NB_RT);
        const int  nb     = is_rec ? NB_RT : NB_ZT;
        const int  nt     = 11 + (is_rec ? (ridx < CUT_RT) : (ridx < CUT_ZT));
        const float* A = is_rec ? output : z;
        const float* B = is_rec ? target : zt;

        if (!is_rec)
            for (int i = t; i < 5 * DZ; i += TPB) ((float*)s_col)[i] = 0.0f;
        __syncthreads();
        unsigned pbits = 0;

        if (t == 0) {
            for (int k = 0; k < NSTG; k++) {
                size_t off = (size_t)(ridx + k * nb) * 4096;
                uint32_t d = smem_u32(&dyn[k * STAGE_FLOATS]);
                mbar_expect(mb[k], STAGE_BYTES);
                bulk_g2s(d,         A + off, 16384, mb[k]);
                bulk_g2s(d + 16384, B + off, 16384, mb[k]);
            }
        }

        if (is_rec) {
            float b = 0.0f;
            int s = 0;
            for (int k = 0; k < nt; k++) {
                mbar_wait(mb[s], (pbits >> s) & 1u);
                pbits ^= (1u << s);
                const float4* base = (const float4*)&dyn[s * STAGE_FLOATS];
                #pragma unroll
                for (int j = 0; j < 2; j++)
                    rec_acc(base[j * 512 + t], base[1024 + j * 512 + t], b);
                __syncthreads();
                if (t == 0 && k + NSTG < nt) {
                    size_t off = (size_t)(ridx + (k + NSTG) * nb) * 4096;
                    uint32_t d = smem_u32(&dyn[s * STAGE_FLOATS]);
                    mbar_expect(mb[s], STAGE_BYTES);
                    bulk_g2s(d,         A + off, 16384, mb[s]);
                    bulk_g2s(d + 16384, B + off, 16384, mb[s]);
                }
                s = (s == NSTG - 1) ? 0 : s + 1;
            }
            #pragma unroll
            for (int off = 16; off; off >>= 1)
                b += __shfl_down_sync(0xFFFFFFFFu, b, off);
            if (lane == 0) s_ab[warp] = b;
            __syncthreads();
            if (t == 0) {
                float tb = 0.0f;
                #pragma unroll
                for (int w = 0; w < 16; w++) tb += s_ab[w];
                atomicAdd(&g_scal[1], tb);
            }
        } else {
            float st[5][4] = {{0}};
            int s = 0;
            for (int k = 0; k < nt; k++) {
                mbar_wait(mb[s], (pbits >> s) & 1u);
                pbits ^= (1u << s);
                const float4* base = (const float4*)&dyn[s * STAGE_FLOATS];
                #pragma unroll
                for (int j = 0; j < 2; j++) {
                    float4 U = base[         j * 512 + t];
                    float4 V = base[1024 +   j * 512 + t];
                    st[0][0] += U.x; st[1][0] += V.x; st[2][0] += U.x * U.x; st[3][0] += V.x * V.x; st[4][0] += U.x * V.x;
                    st[0][1] += U.y; st[1][1] += V.y; st[2][1] += U.y * U.y; st[3][1] += V.y * V.y; st[4][1] += U.y * V.y;
                    st[0][2] += U.z; st[1][2] += V.z; st[2][2] += U.z * U.z; st[3][2] += V.z * V.z; st[4][2] += U.z * V.z;
                    st[0][3] += U.w; st[1][3] += V.w; st[2][3] += U.w * U.w; st[3][3] += V.w * V.w; st[4][3] += U.w * V.w;
                }
                __syncthreads();
                if (t == 0 && k + NSTG < nt) {
                    size_t off = (size_t)(ridx + (k + NSTG) * nb) * 4096;
                    uint32_t d = smem_u32(&dyn[s * STAGE_FLOATS]);
                    mbar_expect(mb[s], STAGE_BYTES);
                    bulk_g2s(d,         A + off, 16384, mb[s]);
                    bulk_g2s(d + 16384, B + off, 16384, mb[s]);
                }
                s = (s == NSTG - 1) ? 0 : s + 1;
            }
            // warp fold: lanes l and l+16 own same columns (512 % 16 == 0)
            #pragma unroll
            for (int si = 0; si < 5; si++)
                #pragma unroll
                for (int c = 0; c < 4; c++)
                    st[si][c] += __shfl_xor_sync(0xFFFFFFFFu, st[si][c], 16);
            if (lane < 16) {
                const int cg = t & 15;
                #pragma unroll
                for (int si = 0; si < 5; si++)
                    #pragma unroll
                    for (int c = 0; c < 4; c++)
                        atomicAdd(&s_col[si][cg * 4 + c], st[si][c]);
            }
            __syncthreads();
            for (int i = t; i < 5 * DZ; i += TPB)
                atomicAdd(&((float*)g_col)[i], ((float*)s_col)[i]);
        }
    } else {
        // =================== LDG path: KL (32MB) + recon slice (16MB) =========
        const int g = (bid - NB_RT - NB_ZT) * TPB + t;   // 0..38911
        float a = 0.0f, b = 0.0f;
        {
            const float4* lv4 = (const float4*)logv;
            const float4* m4  = (const float4*)mean;
            int i = g;
            #pragma unroll
            for (int kk = 0; kk < 13; kk++) {   // 26 = 13*2
                float4 L0 = __ldcs(lv4 + i);
                float4 M0 = __ldcs(m4  + i);
                float4 L1 = __ldcs(lv4 + i + LDG_T);
                float4 M1 = __ldcs(m4  + i + LDG_T);
                kl_acc(L0, M0, a);
                kl_acc(L1, M1, a);
                i += 2 * LDG_T;
            }
            if (g < KL_TAIL) {
                float4 L = __ldcs(lv4 + i), M = __ldcs(m4 + i);
                kl_acc(L, M, a);
            }
        }
        {
            const float4* o4 = (const float4*)output + RS_BASE;
            const float4* t4 = (const float4*)target + RS_BASE;
            int i = g;
            #pragma unroll
            for (int kk = 0; kk < 6; kk++) {    // 12 of 13
                float4 O0 = __ldcs(o4 + i);
                float4 T0 = __ldcs(t4 + i);
                float4 O1 = __ldcs(o4 + i + LDG_T);
                float4 T1 = __ldcs(t4 + i + LDG_T);
                rec_acc(O0, T0, b);
                rec_acc(O1, T1, b);
                i += 2 * LDG_T;
            }
            { float4 O = __ldcs(o4 + i), T = __ldcs(t4 + i); rec_acc(O, T, b); i += LDG_T; }
            if (g < RS_TAIL) {
                float4 O = __ldcs(o4 + i), T = __ldcs(t4 + i);
                rec_acc(O, T, b);
            }
        }

        #pragma unroll
        for (int off = 16; off; off >>= 1) {
            a += __shfl_down_sync(0xFFFFFFFFu, a, off);
            b += __shfl_down_sync(0xFFFFFFFFu, b, off);
        }
        __shared__ float s_b[16];
        if (lane == 0) { s_ab[warp] = a; s_b[warp] = b; }
        __syncthreads();
        if (t == 0) {
            float ta = 0.0f, tb = 0.0f;
            #pragma unroll
            for (int w = 0; w < 16; w++) { ta += s_ab[w]; tb += s_b[w]; }
            atomicAdd(&g_scal[0], ta);
            atomicAdd(&g_scal[1], tb);
        }
    }

    // ================= last block finalizes + resets ==========================
    __shared__ unsigned int s_rank;
    __threadfence();
    __syncthreads();
    if (t == 0) s_rank = atomicAdd(&g_count, 1u);
    __syncthreads();
    if (s_rank != GRID - 1) return;

    __threadfence();

    __shared__ float sc[2], ss[2];
    if (t < DZ) {
        const int d = t;
        const float invN = 1.0f / (float)NROWS;
        float Sz   = *((volatile float*)&g_col[0][d]);
        float Szt  = *((volatile float*)&g_col[1][d]);
        float Sz2  = *((volatile float*)&g_col[2][d]);
        float Szt2 = *((volatile float*)&g_col[3][d]);
        float Szp  = *((volatile float*)&g_col[4][d]);

        float mu = Sz * invN, nu = Szt * invN;
        float cov  = Szp * invN - mu * nu;
        float vart = (Sz2  - (float)NROWS * mu * mu) / (float)(NROWS - 1);
        float varu = (Szt2 - (float)NROWS * nu * nu) / (float)(NROWS - 1);
        float sp = sqrtf(fmaxf(vart * varu, 0.0f));

        #pragma unroll
        for (int off = 16; off; off >>= 1) {
            cov += __shfl_down_sync(0xFFFFFFFFu, cov, off);
            sp  += __shfl_down_sync(0xFFFFFFFFu, sp,  off);
        }
        if (lane == 0) { sc[warp] = cov; ss[warp] = sp; }
    }
    __syncthreads();

    if (t == 0) {
        const float invN = 1.0f / (float)NROWS;
        float num = sc[0] + sc[1];
        float dot = ss[0] + ss[1];
        float kl    = -0.5f * (*((volatile float*)&g_scal[0])) * invN;
        float recon = (*((volatile float*)&g_scal[1])) / (float)((long long)NROWS * DOUT);
        out[0] = recon + kl - num / dot;
    }
    __syncthreads();

    for (int i = t; i < 5 * DZ; i += TPB) ((float*)g_col)[i] = 0.0f;
    if (t == 0) { g_scal[0] = 0.0f; g_scal[1] = 0.0f; g_count = 0u; }
}

extern "C" void kernel_launch(void* const* d_in, const int* in_sizes, int n_in,
                              void* d_out, int out_size) {
    (void)in_sizes; (void)n_in; (void)out_size;
    cudaFuncSetAttribute(vde_fused_kernel,
                         cudaFuncAttributeMaxDynamicSharedMemorySize, DYN_BYTES);
    vde_fused_kernel<<<GRID, TPB, DYN_BYTES>>>(
        (const float*)d_in[0], (const float*)d_in[1],
        (const float*)d_in[2], (const float*)d_in[3],
        (const float*)d_in[4], (const float*)d_in[5],
        (float*)d_out);
}

// round 15
// speedup vs baseline: 1.2684x; 1.1001x over previous
#include <cuda_runtime.h>
#include <cstdint>

#define NROWS 65536
#define DOUT  128
#define DZ    64

#define GRID  304
#define TPB   256
#define NSTG  3

#define STAGE_FLOATS 8192             // 32 KB per stage
#define STAGE_BYTES  32768
#define DYN_BYTES    (NSTG * STAGE_BYTES)   // 98304

// roles via bid%19: r<8 rec-TMA (128 blocks), r<12 z-TMA (64), else KL-LDG (112)
#define NB_REC 128     // 2048 recon tiles -> 16 tiles/block exactly
#define NB_ZZ   64     // 1024 z tiles     -> 16 tiles/block exactly
#define NB_LDG 112
#define NT      16     // tiles per TMA block, uniform

#define LDG_T   (NB_LDG * TPB)       // 28672 threads
#define KL_ITERS 36                  // 1048576 f4 = 36*28672 + 16384
#define KL_TAIL  16384

// Zero-initialized device globals (reset by last block each call -> replay-safe)
__device__ float        g_scal[2];      // [0]=KL elem sum, [1]=recon sq sum
__device__ float        g_col[5][DZ];   // Sz, Szt, Sz2, Szt2, Szp
__device__ unsigned int g_count;

__device__ __forceinline__ uint32_t smem_u32(const void* p) {
    return (uint32_t)__cvta_generic_to_shared((void*)p);
}
__device__ __forceinline__ void mbar_init(uint32_t a, uint32_t cnt) {
    asm volatile("mbarrier.init.shared.b64 [%0], %1;" :: "r"(a), "r"(cnt) : "memory");
}
__device__ __forceinline__ void mbar_expect(uint32_t a, uint32_t bytes) {
    asm volatile("mbarrier.arrive.expect_tx.shared.b64 _, [%0], %1;"
                 :: "r"(a), "r"(bytes) : "memory");
}
__device__ __forceinline__ void bulk_g2s(uint32_t dst, const float* src,
                                         uint32_t bytes, uint32_t mbar) {
    asm volatile(
        "cp.async.bulk.shared::cluster.global.mbarrier::complete_tx::bytes "
        "[%0], [%1], %2, [%3];"
        :: "r"(dst), "l"(src), "r"(bytes), "r"(mbar) : "memory");
}
__device__ __forceinline__ void mbar_wait(uint32_t a, uint32_t parity) {
    asm volatile(
        "{\n\t"
        ".reg .pred P1;\n\t"
        "LAB_WAIT_%=:\n\t"
        "mbarrier.try_wait.parity.acquire.cta.shared::cta.b64 P1, [%0], %1, 0x989680;\n\t"
        "@P1 bra LAB_DONE_%=;\n\t"
        "bra LAB_WAIT_%=;\n\t"
        "LAB_DONE_%=:\n\t"
        "}"
        :: "r"(a), "r"(parity) : "memory");
}

__device__ __forceinline__ void kl_acc(const float4& L, const float4& M, float& a) {
    a += (L.x - __expf(L.x) - M.x * M.x + 1.0f);
    a += (L.y - __expf(L.y) - M.y * M.y + 1.0f);
    a += (L.z - __expf(L.z) - M.z * M.z + 1.0f);
    a += (L.w - __expf(L.w) - M.w * M.w + 1.0f);
}
__device__ __forceinline__ void rec_acc(const float4& O, const float4& T, float& b) {
    float d0 = O.x - T.x, d1 = O.y - T.y, d2 = O.z - T.z, d3 = O.w - T.w;
    b += d0 * d0 + d1 * d1 + d2 * d2 + d3 * d3;
}

extern __shared__ float dyn[];   // NSTG stages of 8192 floats

__global__ void __launch_bounds__(TPB) vde_fused_kernel(
    const float* __restrict__ target,
    const float* __restrict__ output,
    const float* __restrict__ mean,
    const float* __restrict__ logv,
    const float* __restrict__ z,
    const float* __restrict__ zt,
    float* __restrict__ out)
{
    __shared__ __align__(8) unsigned long long mbar_s[NSTG];
    __shared__ float s_part[8][320];
    __shared__ float s_ab[8];

    const int bid  = blockIdx.x;
    const int t    = threadIdx.x;
    const int lane = t & 31;
    const int warp = t >> 5;

    const int grp = bid / 19;
    const int r   = bid % 19;

    if (r < 12) {
        // =================== TMA path =========================================
        uint32_t mb[NSTG];
        #pragma unroll
        for (int s = 0; s < NSTG; s++) mb[s] = smem_u32(&mbar_s[s]);
        if (t == 0) {
            #pragma unroll
            for (int s = 0; s < NSTG; s++) mbar_init(mb[s], 1);
        }
        __syncthreads();
        unsigned pbits = 0;

        const bool is_rec = (r < 8);
        const int  ridx   = is_rec ? (grp * 8 + r) : (grp * 4 + (r - 8));
        const int  nb     = is_rec ? NB_REC : NB_ZZ;
        const float* A = is_rec ? output : z;
        const float* B = is_rec ? target : zt;

        if (t == 0) {
            for (int k = 0; k < NSTG; k++) {
                size_t off = (size_t)(ridx + k * nb) * 4096;
                uint32_t d = smem_u32(&dyn[k * STAGE_FLOATS]);
                mbar_expect(mb[k], STAGE_BYTES);
                bulk_g2s(d,         A + off, 16384, mb[k]);
                bulk_g2s(d + 16384, B + off, 16384, mb[k]);
            }
        }

        if (is_rec) {
            float b = 0.0f;
            int s = 0;
            for (int k = 0; k < NT; k++) {
                mbar_wait(mb[s], (pbits >> s) & 1u);
                pbits ^= (1u << s);
                const float4* base = (const float4*)&dyn[s * STAGE_FLOATS];
                #pragma unroll
                for (int j = 0; j < 4; j++)
                    rec_acc(base[j * 256 + t], base[1024 + j * 256 + t], b);
                __syncthreads();
                if (t == 0 && k + NSTG < NT) {
                    size_t off = (size_t)(ridx + (k + NSTG) * nb) * 4096;
                    uint32_t d = smem_u32(&dyn[s * STAGE_FLOATS]);
                    mbar_expect(mb[s], STAGE_BYTES);
                    bulk_g2s(d,         A + off, 16384, mb[s]);
                    bulk_g2s(d + 16384, B + off, 16384, mb[s]);
                }
                s = (s == NSTG - 1) ? 0 : s + 1;
            }
            #pragma unroll
            for (int off = 16; off; off >>= 1)
                b += __shfl_down_sync(0xFFFFFFFFu, b, off);
            if (lane == 0) s_ab[warp] = b;
            __syncthreads();
            if (t == 0) {
                float tb = 0.0f;
                #pragma unroll
                for (int w = 0; w < 8; w++) tb += s_ab[w];
                atomicAdd(&g_scal[1], tb);
            }
        } else {
            float st[5][4] = {{0}};
            int s = 0;
            for (int k = 0; k < NT; k++) {
                mbar_wait(mb[s], (pbits >> s) & 1u);
                pbits ^= (1u << s);
                const float4* base = (const float4*)&dyn[s * STAGE_FLOATS];
                #pragma unroll
                for (int j = 0; j < 4; j++) {
                    float4 U = base[         j * 256 + t];
                    float4 V = base[1024 +   j * 256 + t];
                    st[0][0] += U.x; st[1][0] += V.x; st[2][0] += U.x * U.x; st[3][0] += V.x * V.x; st[4][0] += U.x * V.x;
                    st[0][1] += U.y; st[1][1] += V.y; st[2][1] += U.y * U.y; st[3][1] += V.y * V.y; st[4][1] += U.y * V.y;
                    st[0][2] += U.z; st[1][2] += V.z; st[2][2] += U.z * U.z; st[3][2] += V.z * V.z; st[4][2] += U.z * V.z;
                    st[0][3] += U.w; st[1][3] += V.w; st[2][3] += U.w * U.w; st[3][3] += V.w * V.w; st[4][3] += U.w * V.w;
                }
                __syncthreads();
                if (t == 0 && k + NSTG < NT) {
                    size_t off = (size_t)(ridx + (k + NSTG) * nb) * 4096;
                    uint32_t d = smem_u32(&dyn[s * STAGE_FLOATS]);
                    mbar_expect(mb[s], STAGE_BYTES);
                    bulk_g2s(d,         A + off, 16384, mb[s]);
                    bulk_g2s(d + 16384, B + off, 16384, mb[s]);
                }
                s = (s == NSTG - 1) ? 0 : s + 1;
            }
            #pragma unroll
            for (int si = 0; si < 5; si++)
                #pragma unroll
                for (int c = 0; c < 4; c++)
                    st[si][c] += __shfl_xor_sync(0xFFFFFFFFu, st[si][c], 16);
            if (lane < 16) {
                #pragma unroll
                for (int si = 0; si < 5; si++)
                    #pragma unroll
                    for (int c = 0; c < 4; c++)
                        s_part[warp][(si * 4 + c) * 16 + lane] = st[si][c];
            }
            __syncthreads();
            for (int idx = t; idx < 320; idx += TPB) {
                float v = 0.0f;
                #pragma unroll
                for (int w = 0; w < 8; w++) v += s_part[w][idx];
                int si  = idx >> 6;
                int rem = idx & 63;
                int c   = rem >> 4;
                int l   = rem & 15;
                atomicAdd(&g_col[si][l * 4 + c], v);
            }
        }
    } else {
        // =================== LDG path: KL (logv + mean, 32 MB) ================
        __syncthreads();
        const int ridx = grp * 7 + (r - 12);     // 0..111
        const int g    = ridx * TPB + t;         // 0..28671
        const float4* lv4 = (const float4*)logv;
        const float4* m4  = (const float4*)mean;

        float a = 0.0f;
        int i = g;
        #pragma unroll
        for (int kk = 0; kk < 9; kk++) {     // 36 = 9*4
            float4 L0 = __ldcs(lv4 + i);
            float4 M0 = __ldcs(m4  + i);
            float4 L1 = __ldcs(lv4 + i +     LDG_T);
            float4 M1 = __ldcs(m4  + i +     LDG_T);
            float4 L2 = __ldcs(lv4 + i + 2 * LDG_T);
            float4 M2 = __ldcs(m4  + i + 2 * LDG_T);
            float4 L3 = __ldcs(lv4 + i + 3 * LDG_T);
            float4 M3 = __ldcs(m4  + i + 3 * LDG_T);
            kl_acc(L0, M0, a); kl_acc(L1, M1, a);
            kl_acc(L2, M2, a); kl_acc(L3, M3, a);
            i += 4 * LDG_T;
        }
        if (g < KL_TAIL) {
            float4 L = __ldcs(lv4 + i), M = __ldcs(m4 + i);
            kl_acc(L, M, a);
        }

        #pragma unroll
        for (int off = 16; off; off >>= 1)
            a += __shfl_down_sync(0xFFFFFFFFu, a, off);
        if (lane == 0) s_ab[warp] = a;
        __syncthreads();
        if (t == 0) {
            float ta = 0.0f;
            #pragma unroll
            for (int w = 0; w < 8; w++) ta += s_ab[w];
            atomicAdd(&g_scal[0], ta);
        }
    }

    // ================= last block finalizes + resets ==========================
    __shared__ unsigned int s_rank;
    __threadfence();
    __syncthreads();
    if (t == 0) s_rank = atomicAdd(&g_count, 1u);
    __syncthreads();
    if (s_rank != GRID - 1) return;

    __threadfence();

    __shared__ float sc[2], ss[2];
    if (t < DZ) {
        const int d = t;
        const float invN = 1.0f / (float)NROWS;
        float Sz   = *((volatile float*)&g_col[0][d]);
        float Szt  = *((volatile float*)&g_col[1][d]);
        float Sz2  = *((volatile float*)&g_col[2][d]);
        float Szt2 = *((volatile float*)&g_col[3][d]);
        float Szp  = *((volatile float*)&g_col[4][d]);

        float mu = Sz * invN, nu = Szt * invN;
        float cov  = Szp * invN - mu * nu;
        float vart = (Sz2  - (float)NROWS * mu * mu) / (float)(NROWS - 1);
        float varu = (Szt2 - (float)NROWS * nu * nu) / (float)(NROWS - 1);
        float sp = sqrtf(fmaxf(vart * varu, 0.0f));

        #pragma unroll
        for (int off = 16; off; off >>= 1) {
            cov += __shfl_down_sync(0xFFFFFFFFu, cov, off);
            sp  += __shfl_down_sync(0xFFFFFFFFu, sp,  off);
        }
        if (lane == 0) { sc[warp] = cov; ss[warp] = sp; }
    }
    __syncthreads();

    if (t == 0) {
        const float invN = 1.0f / (float)NROWS;
        float num = sc[0] + sc[1];
        float dot = ss[0] + ss[1];
        float kl    = -0.5f * (*((volatile float*)&g_scal[0])) * invN;
        float recon = (*((volatile float*)&g_scal[1])) / (float)((long long)NROWS * DOUT);
        out[0] = recon + kl - num / dot;
    }
    __syncthreads();

    for (int i = t; i < 5 * DZ; i += TPB) ((float*)g_col)[i] = 0.0f;
    if (t == 0) { g_scal[0] = 0.0f; g_scal[1] = 0.0f; g_count = 0u; }
}

extern "C" void kernel_launch(void* const* d_in, const int* in_sizes, int n_in,
                              void* d_out, int out_size) {
    (void)in_sizes; (void)n_in; (void)out_size;
    cudaFuncSetAttribute(vde_fused_kernel,
                         cudaFuncAttributeMaxDynamicSharedMemorySize, DYN_BYTES);
    vde_fused_kernel<<<GRID, TPB, DYN_BYTES>>>(
        (const float*)d_in[0], (const float*)d_in[1],
        (const float*)d_in[2], (const float*)d_in[3],
        (const float*)d_in[4], (const float*)d_in[5],
        (float*)d_out);
}